// round 1
// baseline (speedup 1.0000x reference)
#include <cuda_runtime.h>
#include <math.h>

// SupConLoss fused kernel for B=8192, D=128, T=0.1.
// One pass over the implicit 8192x8192 similarity matrix with online softmax
// row statistics; never materializes sim.

#define BSZ   8192
#define DD    128
#define BM    64
#define BN    64
#define PAD   72          // padded row length of transposed smem tiles [128][72]
#define NTHR  256
#define INV_T 10.0f

// global accumulators (device globals: no allocation allowed)
__device__ float g_sum;
__device__ float g_cnt;

__global__ void supcon_zero_kernel() {
    g_sum = 0.0f;
    g_cnt = 0.0f;
}

__global__ void supcon_finalize_kernel(float* __restrict__ out) {
    float c = g_cnt;
    out[0] = (c > 0.0f) ? (g_sum / c) : 0.0f;
}

extern __shared__ float smem[];

__global__ __launch_bounds__(NTHR)
void supcon_main_kernel(const float* __restrict__ F,
                        const long long* __restrict__ L) {
    float* As = smem;                       // [DD][PAD]  (k-major, transposed)
    float* Bs = smem + DD * PAD;            // [DD][PAD]
    int*   labA = (int*)(smem + 2 * DD * PAD);   // [BM]
    int*   labB = labA + BM;                     // [BN]

    const int tid = threadIdx.x;
    const int tx  = tid & 15;               // 0..15 -> column group
    const int ty  = tid >> 4;               // 0..15 -> row group
    const int row0 = blockIdx.x * BM;

    // ---- load A tile (this block's anchor rows), transposed into smem ----
    {
        const int c = tid >> 2;             // 0..63 local row
        const int q = tid & 3;
        const float4* src = (const float4*)(F + (size_t)(row0 + c) * DD);
        #pragma unroll
        for (int i = 0; i < 8; i++) {
            int kf = q + i * 4;             // 0..31 float4 index along D
            float4 v = src[kf];
            int k = kf * 4;
            As[(k + 0) * PAD + c] = v.x;
            As[(k + 1) * PAD + c] = v.y;
            As[(k + 2) * PAD + c] = v.z;
            As[(k + 3) * PAD + c] = v.w;
        }
        if (tid < BM) labA[tid] = (int)L[row0 + tid];
    }

    // per-thread running row state for rows ty*4+i (replicated across the 16
    // lanes sharing ty; they all compute identical reduced values)
    float m[4], s[4], ps[4], pc[4];
    #pragma unroll
    for (int i = 0; i < 4; i++) {
        m[i] = -INFINITY; s[i] = 0.0f; ps[i] = 0.0f; pc[i] = 0.0f;
    }

    const int la0 = ty * 4;

    for (int jt = 0; jt < BSZ / BN; jt++) {
        const int col0 = jt * BN;
        __syncthreads();                    // guard Bs reuse (and As visibility on jt=0)

        // ---- load B tile, transposed ----
        {
            const int c = tid >> 2;
            const int q = tid & 3;
            const float4* src = (const float4*)(F + (size_t)(col0 + c) * DD);
            #pragma unroll
            for (int i = 0; i < 8; i++) {
                int kf = q + i * 4;
                float4 v = src[kf];
                int k = kf * 4;
                Bs[(k + 0) * PAD + c] = v.x;
                Bs[(k + 1) * PAD + c] = v.y;
                Bs[(k + 2) * PAD + c] = v.z;
                Bs[(k + 3) * PAD + c] = v.w;
            }
            if (tid < BN) labB[tid] = (int)L[col0 + tid];
        }
        __syncthreads();

        // ---- 4x4 register-tiled GEMM: acc[i][j] = dot(f_row, f_col) ----
        float acc[4][4];
        #pragma unroll
        for (int i = 0; i < 4; i++)
            #pragma unroll
            for (int j = 0; j < 4; j++) acc[i][j] = 0.0f;

        #pragma unroll 4
        for (int k = 0; k < DD; k++) {
            float4 a = *(const float4*)&As[k * PAD + ty * 4];
            float4 b = *(const float4*)&Bs[k * PAD + tx * 4];
            float av[4] = {a.x, a.y, a.z, a.w};
            float bv[4] = {b.x, b.y, b.z, b.w};
            #pragma unroll
            for (int i = 0; i < 4; i++)
                #pragma unroll
                for (int j = 0; j < 4; j++)
                    acc[i][j] = fmaf(av[i], bv[j], acc[i][j]);
        }

        // column labels for this thread's 4 columns
        int lb[4];
        #pragma unroll
        for (int j = 0; j < 4; j++) lb[j] = labB[tx * 4 + j];

        // ---- per-row reduction over this 64-col tile + online merge ----
        #pragma unroll
        for (int i = 0; i < 4; i++) {
            const int gi = row0 + la0 + i;
            const int la = labA[la0 + i];

            // tile max (diag INCLUDED, matching reference)
            float vm = -INFINITY;
            #pragma unroll
            for (int j = 0; j < 4; j++) vm = fmaxf(vm, acc[i][j] * INV_T);
            #pragma unroll
            for (int off = 8; off >= 1; off >>= 1)
                vm = fmaxf(vm, __shfl_xor_sync(0xffffffffu, vm, off));

            // exp-sum (diag excluded), positive sum & count
            float ls = 0.0f, lp = 0.0f, lc = 0.0f;
            #pragma unroll
            for (int j = 0; j < 4; j++) {
                const int gj = col0 + tx * 4 + j;
                const float v = acc[i][j] * INV_T;
                if (gj != gi) {
                    ls += __expf(v - vm);
                    if (lb[j] == la) { lp += v; lc += 1.0f; }
                }
            }
            #pragma unroll
            for (int off = 8; off >= 1; off >>= 1) {
                ls += __shfl_xor_sync(0xffffffffu, ls, off);
                lp += __shfl_xor_sync(0xffffffffu, lp, off);
                lc += __shfl_xor_sync(0xffffffffu, lc, off);
            }

            // online-softmax merge into running state
            const float mn = fmaxf(m[i], vm);
            s[i]  = s[i] * __expf(m[i] - mn) + ls * __expf(vm - mn);
            m[i]  = mn;
            ps[i] += lp;
            pc[i] += lc;
        }
    }

    // ---- per-row contribution -> global accumulators ----
    if (tx == 0) {
        #pragma unroll
        for (int i = 0; i < 4; i++) {
            if (pc[i] > 0.0f) {
                float mean_lp = ps[i] / pc[i] - m[i] - logf(s[i] + 1e-12f);
                atomicAdd(&g_sum, -mean_lp);
                atomicAdd(&g_cnt, 1.0f);
            }
        }
    }
}

extern "C" void kernel_launch(void* const* d_in, const int* in_sizes, int n_in,
                              void* d_out, int out_size) {
    const float*     F = (const float*)d_in[0];
    const long long* L = (const long long*)d_in[1];
    float*           out = (float*)d_out;

    const int smem_bytes = 2 * DD * PAD * sizeof(float) + (BM + BN) * sizeof(int);
    cudaFuncSetAttribute(supcon_main_kernel,
                         cudaFuncAttributeMaxDynamicSharedMemorySize, smem_bytes);

    supcon_zero_kernel<<<1, 1>>>();
    supcon_main_kernel<<<BSZ / BM, NTHR, smem_bytes>>>(F, L);
    supcon_finalize_kernel<<<1, 1>>>(out);
}